// round 9
// baseline (speedup 1.0000x reference)
#include <cuda_runtime.h>

// UnPooling: stride-2 zero-insertion unpool.
// in:  [B=32, H=112, W=112, C=64] fp32
// out: [B=32, 224, 224, 64] fp32; out[b, 2h, 2w, c] = in[b, h, w, c], else 0.
//
// R2 shape (output-driven, linear store stream, odd-row zero-fill fast path)
// at finer granularity: 512 threads, ONE float4 per thread.
// Grid (7, 224, 32): x = 512-f4 chunk of the row, y = output row, z = batch.
//
// Session findings baked in:
//  - 128-bit accesses only (v8/256-bit inflates L1tex wavefronts: DRAM 77->65%).
//  - Store stream must stay warp-linear (input-driven scatter: DRAM 77->67%).
//  - .cs policy: neutral-to-marginally-better (output is 3.3x L2).
//  - More per-thread MLP is neutral/worse (queues saturated by occupancy).
// Pinned at ~457MB effective @ ~6.1TB/s = mixed-R/W HBM turnaround ceiling.

constexpr int B     = 32;
constexpr int H     = 112;
constexpr int C4    = 16;          // 64 floats = 16 float4 per pixel
constexpr int OH    = 224;
constexpr int ROW4  = 224 * C4;    // 3584 float4 per output row
constexpr int IROW4 = 112 * C4;    // 1792 float4 per input row
constexpr int CHUNK = 512;         // float4 per block (1 per thread)

__global__ void __launch_bounds__(512)
unpool_zi_kernel(const float4* __restrict__ in, float4* __restrict__ out)
{
    const unsigned j  = blockIdx.x * (unsigned)CHUNK + threadIdx.x;
    const unsigned oh = blockIdx.y;
    const unsigned b  = blockIdx.z;

    float4* orow = out + (size_t)(b * OH + oh) * ROW4;

    float4 v = make_float4(0.f, 0.f, 0.f, 0.f);

    if (!(oh & 1u)) {
        const unsigned ow = j >> 4;
        if (!(ow & 1u)) {
            const float4* irow = in + (size_t)(b * H + (oh >> 1)) * IROW4;
            v = __ldcs(irow + (ow >> 1) * C4 + (j & 15u));
        }
    }

    __stcs(orow + j, v);
}

extern "C" void kernel_launch(void* const* d_in, const int* in_sizes, int n_in,
                              void* d_out, int out_size)
{
    const float4* in  = (const float4*)d_in[0];
    float4*       out = (float4*)d_out;

    dim3 grid(ROW4 / CHUNK, OH, B);   // (7, 224, 32)
    unpool_zi_kernel<<<grid, 512>>>(in, out);
}

// round 11
// speedup vs baseline: 1.0349x; 1.0349x over previous
#include <cuda_runtime.h>

// UnPooling: stride-2 zero-insertion unpool. FINAL (R2 shape — measured
// optimum of the full design sweep, see table below).
// in:  [B=32, H=112, W=112, C=64] fp32
// out: [B=32, 224, 224, 64] fp32; out[b, 2h, 2w, c] = in[b, h, w, c], else 0.
//
// Output-driven mapping; the 411MB store stream is perfectly linear per warp.
// Grid (7, 224, 32): x = 512-float4 chunk of the output row, y = output row,
// z = batch. Odd rows: pure zero-fill fast path (no loads, no index math).
// Even rows: 2 float4 per thread, loads predicated on even output pixel.
//
// Session sweep (ncu µs / DRAM%):
//   256x1 f4 flat(div/mod) 77.1/74.3 | 256x2 f4 (THIS) 74.7/77.1
//   256x4 f4 row-pair      76.0/75.6 | 512x1 f4        81.2/70.6
//   256x1 v8 256-bit       87.4/65.5 | input-driven    85.7/66.9
//   default-store policy   74.8/76.8 (neutral)
// Conclusions: 128-bit accesses only (wider inflates L1tex wavefronts);
// store stream must stay warp-linear; 256 thr x 2 elem is the granularity
// optimum from both sides. Pinned at ~457MB effective @ ~6.1TB/s = mixed
// R/W HBM turnaround ceiling; compute pipes idle, issue 13% — no kernel-side
// lever remains.

constexpr int B     = 32;
constexpr int H     = 112;
constexpr int C4    = 16;          // 64 floats = 16 float4 per pixel
constexpr int OH    = 224;
constexpr int ROW4  = 224 * C4;    // 3584 float4 per output row
constexpr int IROW4 = 112 * C4;    // 1792 float4 per input row
constexpr int CHUNK = 512;         // float4 per block (2 per thread)

__global__ void __launch_bounds__(256)
unpool_zi_kernel(const float4* __restrict__ in, float4* __restrict__ out)
{
    const unsigned tid  = threadIdx.x;
    const unsigned oh   = blockIdx.y;
    const unsigned b    = blockIdx.z;
    const unsigned base = blockIdx.x * (unsigned)CHUNK + tid;

    float4* orow = out + (size_t)(b * OH + oh) * ROW4;

    const float4 z = make_float4(0.f, 0.f, 0.f, 0.f);

    if (oh & 1u) {
        // Entire row is zero: pure streaming store, no loads.
        __stcs(orow + base,        z);
        __stcs(orow + base + 256u, z);
        return;
    }

    const float4* irow = in + (size_t)(b * H + (oh >> 1)) * IROW4;

    const unsigned j0 = base;
    const unsigned j1 = base + 256u;

    const unsigned ow0 = j0 >> 4, c40 = j0 & 15u;
    const unsigned ow1 = j1 >> 4, c41 = j1 & 15u;

    float4 v0 = z, v1 = z;
    if (!(ow0 & 1u)) v0 = __ldcs(irow + (ow0 >> 1) * C4 + c40);
    if (!(ow1 & 1u)) v1 = __ldcs(irow + (ow1 >> 1) * C4 + c41);

    __stcs(orow + j0, v0);
    __stcs(orow + j1, v1);
}

extern "C" void kernel_launch(void* const* d_in, const int* in_sizes, int n_in,
                              void* d_out, int out_size)
{
    const float4* in  = (const float4*)d_in[0];
    float4*       out = (float4*)d_out;

    dim3 grid(ROW4 / CHUNK, OH, B);   // (7, 224, 32)
    unpool_zi_kernel<<<grid, 256>>>(in, out);
}

// round 12
// speedup vs baseline: 1.0496x; 1.0142x over previous
#include <cuda_runtime.h>

// UnPooling: stride-2 zero-insertion unpool. FINAL.
// in:  [B=32, H=112, W=112, C=64] fp32
// out: [B=32, 224, 224, 64] fp32; out[b, 2h, 2w, c] = in[b, h, w, c], else 0.
//
// R2 shape — measured optimum of the full design sweep:
//   output-driven mapping, 411MB store stream perfectly warp-linear,
//   grid (7, 224, 32): x = 512-f4 chunk, y = output row, z = batch,
//   odd rows = pure zero-fill fast path, even rows = 2 f4/thread.
// Refinement: j1 = j0 + 256 shares c4 AND pixel parity with j0
//   (256 % 16 == 0, (j1>>4) = (j0>>4)+16), so ONE predicate covers both
//   loads and the second address is the first + 128 f4 — shorter ALU
//   critical path before the first LDG.
//
// Sweep results (ncu µs / DRAM%):
//   256x1 flat 77.1/74.3 | 256x2 (THIS) 74.7/77.1 | 256x4 76.0/75.6
//   512x1 81.2/70.6 | v8-256bit 87.4/65.5 | input-driven 85.7/66.9
//   default-store 74.8/76.8 (neutral)
// Pinned at ~457MB effective @ ~6.1TB/s — mixed-R/W HBM turnaround ceiling.

constexpr int B     = 32;
constexpr int H     = 112;
constexpr int C4    = 16;          // 64 floats = 16 float4 per pixel
constexpr int OH    = 224;
constexpr int ROW4  = 224 * C4;    // 3584 float4 per output row
constexpr int IROW4 = 112 * C4;    // 1792 float4 per input row
constexpr int CHUNK = 512;         // float4 per block (2 per thread)

__global__ void __launch_bounds__(256)
unpool_zi_kernel(const float4* __restrict__ in, float4* __restrict__ out)
{
    const unsigned tid  = threadIdx.x;
    const unsigned oh   = blockIdx.y;
    const unsigned b    = blockIdx.z;
    const unsigned base = blockIdx.x * (unsigned)CHUNK + tid;

    float4* orow = out + (size_t)(b * OH + oh) * ROW4;

    const float4 z = make_float4(0.f, 0.f, 0.f, 0.f);

    if (oh & 1u) {
        // Entire row is zero: pure streaming store, no loads.
        __stcs(orow + base,        z);
        __stcs(orow + base + 256u, z);
        return;
    }

    // Even output row. Elements base and base+256 share c4 and pixel parity.
    const unsigned ow0 = base >> 4;
    const unsigned c4  = base & 15u;

    float4 v0 = z, v1 = z;
    if (!(ow0 & 1u)) {
        const float4* p = in + (size_t)(b * H + (oh >> 1)) * IROW4
                             + (ow0 >> 1) * C4 + c4;
        v0 = __ldcs(p);
        v1 = __ldcs(p + 8u * C4);   // (ow0+16)>>1 = (ow0>>1)+8 pixels ahead
    }

    __stcs(orow + base,        v0);
    __stcs(orow + base + 256u, v1);
}

extern "C" void kernel_launch(void* const* d_in, const int* in_sizes, int n_in,
                              void* d_out, int out_size)
{
    const float4* in  = (const float4*)d_in[0];
    float4*       out = (float4*)d_out;

    dim3 grid(ROW4 / CHUNK, OH, B);   // (7, 224, 32)
    unpool_zi_kernel<<<grid, 256>>>(in, out);
}